// round 3
// baseline (speedup 1.0000x reference)
#include <cuda_runtime.h>

#define N_NODES 10000
#define N_EDGES 640000
#define C 128

// Scratch (allocation-free rule: __device__ globals)
__device__ float g_hs[N_NODES * C];      // (x @ W^T) * dis[row]
__device__ int   g_indeg[N_NODES];
__device__ int   g_cursor[N_NODES];
__device__ int   g_rowptr[N_NODES + 1];
__device__ float g_dis[N_NODES];
__device__ int   g_csr[N_EDGES];         // src node per CSR slot (grouped by dst)

__global__ void k_init() {
    int i = blockIdx.x * blockDim.x + threadIdx.x;
    if (i < N_NODES) { g_indeg[i] = 0; g_cursor[i] = 0; }
}

__global__ void k_count(const int* __restrict__ ei) {
    int e = blockIdx.x * blockDim.x + threadIdx.x;
    if (e < N_EDGES) atomicAdd(&g_indeg[ei[N_EDGES + e]], 1);  // col = dst
}

// Single-block scan over 10000 counts -> row_ptr, plus dis = rsqrt(indeg+1)
__global__ void k_scan() {
    __shared__ int sh[1024];
    const int CH = 10;                    // 1024 * 10 >= 10000
    int t = threadIdx.x;
    int base = t * CH;
    int s = 0;
    for (int j = 0; j < CH; j++) {
        int i = base + j;
        if (i < N_NODES) s += g_indeg[i];
    }
    sh[t] = s;
    __syncthreads();
    for (int d = 1; d < 1024; d <<= 1) {
        int v = (t >= d) ? sh[t - d] : 0;
        __syncthreads();
        sh[t] += v;
        __syncthreads();
    }
    int off = sh[t] - s;                  // exclusive prefix of this thread's chunk
    int run = off;
    for (int j = 0; j < CH; j++) {
        int i = base + j;
        if (i < N_NODES) {
            g_rowptr[i] = run;
            int d = g_indeg[i];
            run += d;
            g_dis[i] = rsqrtf((float)(d + 1));   // +1 self-loop
        }
    }
    if (base == N_NODES) g_rowptr[N_NODES] = off;  // thread 1000: total edge count
}

__global__ void k_fill(const int* __restrict__ ei) {
    int e = blockIdx.x * blockDim.x + threadIdx.x;
    if (e < N_EDGES) {
        int c = ei[N_EDGES + e];
        int pos = g_rowptr[c] + atomicAdd(&g_cursor[c], 1);
        g_csr[pos] = ei[e];               // row = src
    }
}

// h = x @ W^T, scaled by dis[node]. Thread = out channel (W row in registers),
// block processes 64 nodes with the x tile broadcast from shared memory.
__global__ void __launch_bounds__(128, 2) k_gemm(const float* __restrict__ x,
                                                 const float* __restrict__ W) {
    __shared__ float4 xs[64 * 32];        // 64 nodes x 128 floats = 32 KB
    int t = threadIdx.x;                  // output channel
    int node0 = blockIdx.x * 64;
    int nmax = min(64, N_NODES - node0);

    float4 w[32];                         // W[t][0..127] in registers
    const float4* W4 = (const float4*)(W + t * C);
#pragma unroll
    for (int k = 0; k < 32; k++) w[k] = W4[k];

    const float4* x4 = (const float4*)(x + (long)node0 * C);
    for (int idx = t; idx < nmax * 32; idx += 128) xs[idx] = x4[idx];
    __syncthreads();

    for (int n = 0; n < nmax; n++) {
        float acc = 0.f;
#pragma unroll
        for (int k = 0; k < 32; k++) {
            float4 xv = xs[n * 32 + k];   // warp-uniform address -> broadcast
            acc += w[k].x * xv.x + w[k].y * xv.y + w[k].z * xv.z + w[k].w * xv.w;
        }
        int node = node0 + n;
        g_hs[node * C + t] = acc * g_dis[node];
    }
}

// One block per destination node; 4-way unrolled gather for MLP.
// hs table is 5.1 MB -> L2-resident; gathers hit L2, no HBM pressure.
__global__ void k_agg(const float* __restrict__ b, float* __restrict__ out) {
    int v = blockIdx.x;
    int t = threadIdx.x;
    int beg = g_rowptr[v], end = g_rowptr[v + 1];
    float acc0 = g_hs[v * C + t];         // self-loop term
    float acc1 = 0.f, acc2 = 0.f, acc3 = 0.f;
    int e = beg;
    for (; e + 4 <= end; e += 4) {
        int s0 = g_csr[e];
        int s1 = g_csr[e + 1];
        int s2 = g_csr[e + 2];
        int s3 = g_csr[e + 3];
        acc0 += g_hs[s0 * C + t];
        acc1 += g_hs[s1 * C + t];
        acc2 += g_hs[s2 * C + t];
        acc3 += g_hs[s3 * C + t];
    }
    for (; e < end; e++) acc0 += g_hs[g_csr[e] * C + t];
    out[v * C + t] = (acc0 + acc1 + acc2 + acc3) * g_dis[v] + b[t];
}

extern "C" void kernel_launch(void* const* d_in, const int* in_sizes, int n_in,
                              void* d_out, int out_size) {
    const float* x  = (const float*)d_in[0];
    const int*   ei = (const int*)d_in[1];
    const float* W  = (const float*)d_in[2];
    const float* b  = (const float*)d_in[3];
    float* out = (float*)d_out;

    k_init<<<(N_NODES + 255) / 256, 256>>>();
    k_count<<<(N_EDGES + 255) / 256, 256>>>(ei);
    k_scan<<<1, 1024>>>();
    k_fill<<<(N_EDGES + 255) / 256, 256>>>(ei);
    k_gemm<<<(N_NODES + 63) / 64, 128>>>(x, W);
    k_agg<<<N_NODES, 128>>>(b, out);
}